// round 3
// baseline (speedup 1.0000x reference)
#include <cuda_runtime.h>
#include <cuda_bf16.h>

#define NN 512
#define EE (NN * NN)

// ---------------- scratch (static __device__, no allocation) ----------------
__device__ int   g_is64;          // 1 if edge_index is int64, 0 if int32
__device__ int   g_nonzero;
__device__ int   g_cnt[NN];
__device__ int   g_off[NN];
__device__ int   g_start[NN + 1];
__device__ float g_invcnt[NN];
__device__ int   g_src_sorted[EE];
__device__ __align__(16) float g_ea_sorted[EE * 8];
__device__ __align__(16) float g_h1[NN * 36];
__device__ __align__(16) float g_h2[NN * 24];
__device__ __align__(16) float g_h3[NN * 5];

// ---------------- packed f32x2 helpers ----------------
__device__ __forceinline__ unsigned long long pk2(float lo, float hi) {
    unsigned long long r;
    asm("mov.b64 %0,{%1,%2};" : "=l"(r) : "f"(lo), "f"(hi));
    return r;
}
__device__ __forceinline__ void upk2(unsigned long long v, float& lo, float& hi) {
    asm("mov.b64 {%0,%1},%2;" : "=f"(lo), "=f"(hi) : "l"(v));
}
__device__ __forceinline__ unsigned long long ffma2(unsigned long long a,
                                                    unsigned long long b,
                                                    unsigned long long c) {
    unsigned long long d;
    asm("fma.rn.f32x2 %0,%1,%2,%3;" : "=l"(d) : "l"(a), "l"(b), "l"(c));
    return d;
}

// index helpers given dtype flag
__device__ __forceinline__ int load_src(const int* raw, int e, int is64) {
    return (is64 ? raw[2 * e] : raw[e]) & (NN - 1);
}
__device__ __forceinline__ int load_dst(const int* raw, int e, int is64) {
    return (is64 ? raw[2 * EE + 2 * e] : raw[EE + e]) & (NN - 1);
}

// ---------------- dtype detect + zero ----------------
__global__ void detect_kernel(const int* __restrict__ raw) {
    int t = threadIdx.x;
    if (t == 0) g_nonzero = 0;
    if (t < NN) g_cnt[t] = 0;
    __syncthreads();
    // sample 256 odd words spread across the buffer's first half (int32-safe range)
    int idx = 2 * (t * (EE / 512)) + 1;   // < EE always, valid for int32 buffer too
    if (t < 256 && raw[idx] != 0) atomicOr(&g_nonzero, 1);
    __syncthreads();
    if (t == 0) g_is64 = (g_nonzero == 0) ? 1 : 0;
}

// ---------------- histogram of dst ----------------
__global__ void hist_kernel(const int* __restrict__ raw) {
    __shared__ int h[NN];
    int tid = threadIdx.x;
    int is64 = g_is64;
    for (int i = tid; i < NN; i += blockDim.x) h[i] = 0;
    __syncthreads();
    int base = blockIdx.x * 1024;
#pragma unroll
    for (int k = 0; k < 4; k++) {
        int e = base + k * 256 + tid;
        atomicAdd(&h[load_dst(raw, e, is64)], 1);
    }
    __syncthreads();
    for (int i = tid; i < NN; i += blockDim.x)
        if (h[i]) atomicAdd(&g_cnt[i], h[i]);
}

// ---------------- exclusive scan (single block of 512) ----------------
__global__ void scan_kernel() {
    __shared__ int sc[NN];
    int t = threadIdx.x;
    int c = g_cnt[t];
    sc[t] = c;
    __syncthreads();
    for (int off = 1; off < NN; off <<= 1) {
        int v = (t >= off) ? sc[t - off] : 0;
        __syncthreads();
        sc[t] += v;
        __syncthreads();
    }
    int excl = sc[t] - c;
    g_start[t] = excl;
    g_off[t]   = excl;
    if (t == NN - 1) g_start[NN] = sc[t];
    g_invcnt[t] = 1.0f / (float)(c > 1 ? c : 1);
}

// ---------------- scatter: counting-sort edges by dst ----------------
__global__ void scatter_kernel(const int* __restrict__ raw,
                               const float* __restrict__ ea) {
    int e = blockIdx.x * 256 + threadIdx.x;
    int is64 = g_is64;
    int d = load_dst(raw, e, is64);
    int pos = atomicAdd(&g_off[d], 1);
    g_src_sorted[pos] = load_src(raw, e, is64);
    const float* p = ea + (size_t)e * 6;
    float* q = g_ea_sorted + (size_t)pos * 8;
    q[0] = p[0]; q[1] = p[1]; q[2] = p[2];
    q[3] = p[3]; q[4] = p[4]; q[5] = p[5];
    q[6] = 0.0f; q[7] = 0.0f;
}

// ---------------- fused NNConv layer (gather form) ----------------
// out_n = relu( mean_{e: dst=n} x[src_e] @ relu(ea_e @ W + b)  + x_n @ root + bias )
template <int IN, int OUT, int OPAD, int BLOCK>
__global__ void __launch_bounds__(BLOCK) nnconv_kernel(
    const float* __restrict__ h_in,
    const float* __restrict__ W, const float* __restrict__ b,
    const float* __restrict__ root, const float* __restrict__ bias,
    float* __restrict__ h_out) {
    constexpr int NP = OPAD / 2;
    __shared__ __align__(16) float sW[IN * NP * 16];
    __shared__ float red[BLOCK / 32][OPAD];
    const int tid = threadIdx.x;

    // Stage W+b into smem, packed as (o even, o odd) pairs per (i, o-pair) tile:
    // tile = [w0lo,w0hi, w1lo,w1hi, ..., w5lo,w5hi, blo,bhi, pad,pad]  (64 B)
    for (int idx = tid; idx < IN * NP; idx += BLOCK) {
        int i = idx / NP, p = idx % NP;
        float* t = sW + idx * 16;
        int o0 = 2 * p, o1 = 2 * p + 1;
#pragma unroll
        for (int v = 0; v < 6; v++) {
            t[2 * v]     = (o0 < OUT) ? W[v * (IN * OUT) + i * OUT + o0] : 0.0f;
            t[2 * v + 1] = (o1 < OUT) ? W[v * (IN * OUT) + i * OUT + o1] : 0.0f;
        }
        t[12] = (o0 < OUT) ? b[i * OUT + o0] : 0.0f;
        t[13] = (o1 < OUT) ? b[i * OUT + o1] : 0.0f;
        t[14] = 0.0f; t[15] = 0.0f;
    }
    __syncthreads();

    const int n = blockIdx.x;
    const int e0 = g_start[n], e1 = g_start[n + 1];

    float acc[OPAD];
#pragma unroll
    for (int o = 0; o < OPAD; o++) acc[o] = 0.0f;

    for (int e = e0 + tid; e < e1; e += BLOCK) {
        int s = g_src_sorted[e];
        float4 eaA = *(const float4*)(g_ea_sorted + (size_t)e * 8);
        float4 eaB = *(const float4*)(g_ea_sorted + (size_t)e * 8 + 4);
        unsigned long long ea2[6];
        ea2[0] = pk2(eaA.x, eaA.x); ea2[1] = pk2(eaA.y, eaA.y);
        ea2[2] = pk2(eaA.z, eaA.z); ea2[3] = pk2(eaA.w, eaA.w);
        ea2[4] = pk2(eaB.x, eaB.x); ea2[5] = pk2(eaB.y, eaB.y);

        if constexpr (IN == 1) {
            float xi = h_in[s];
            const ulonglong2* tp = (const ulonglong2*)sW;
#pragma unroll
            for (int p = 0; p < NP; p++) {
                ulonglong2 w01 = tp[4 * p + 0];
                ulonglong2 w23 = tp[4 * p + 1];
                ulonglong2 w45 = tp[4 * p + 2];
                ulonglong2 bb  = tp[4 * p + 3];
                unsigned long long t = bb.x;
                t = ffma2(ea2[0], w01.x, t);
                t = ffma2(ea2[1], w01.y, t);
                t = ffma2(ea2[2], w23.x, t);
                t = ffma2(ea2[3], w23.y, t);
                t = ffma2(ea2[4], w45.x, t);
                t = ffma2(ea2[5], w45.y, t);
                float t0, t1; upk2(t, t0, t1);
                acc[2 * p]     = fmaf(xi, fmaxf(t0, 0.0f), acc[2 * p]);
                acc[2 * p + 1] = fmaf(xi, fmaxf(t1, 0.0f), acc[2 * p + 1]);
            }
        } else {
#pragma unroll 1
            for (int i4 = 0; i4 < IN / 4; i4++) {
                float4 xv = *(const float4*)(h_in + (size_t)s * IN + 4 * i4);
                float xs[4] = {xv.x, xv.y, xv.z, xv.w};
#pragma unroll
                for (int su = 0; su < 4; su++) {
                    float xi = xs[su];
                    const ulonglong2* tp =
                        (const ulonglong2*)(sW + (size_t)(i4 * 4 + su) * NP * 16);
#pragma unroll
                    for (int p = 0; p < NP; p++) {
                        ulonglong2 w01 = tp[4 * p + 0];
                        ulonglong2 w23 = tp[4 * p + 1];
                        ulonglong2 w45 = tp[4 * p + 2];
                        ulonglong2 bb  = tp[4 * p + 3];
                        unsigned long long t = bb.x;
                        t = ffma2(ea2[0], w01.x, t);
                        t = ffma2(ea2[1], w01.y, t);
                        t = ffma2(ea2[2], w23.x, t);
                        t = ffma2(ea2[3], w23.y, t);
                        t = ffma2(ea2[4], w45.x, t);
                        t = ffma2(ea2[5], w45.y, t);
                        float t0, t1; upk2(t, t0, t1);
                        acc[2 * p]     = fmaf(xi, fmaxf(t0, 0.0f), acc[2 * p]);
                        acc[2 * p + 1] = fmaf(xi, fmaxf(t1, 0.0f), acc[2 * p + 1]);
                    }
                }
            }
        }
    }

    // warp reduce
#pragma unroll
    for (int o = 0; o < OPAD; o++) {
        float v = acc[o];
        v += __shfl_down_sync(0xffffffffu, v, 16);
        v += __shfl_down_sync(0xffffffffu, v, 8);
        v += __shfl_down_sync(0xffffffffu, v, 4);
        v += __shfl_down_sync(0xffffffffu, v, 2);
        v += __shfl_down_sync(0xffffffffu, v, 1);
        acc[o] = v;
    }
    if ((tid & 31) == 0) {
#pragma unroll
        for (int o = 0; o < OPAD; o++) red[tid >> 5][o] = acc[o];
    }
    __syncthreads();

    if (tid < OUT) {
        float s = 0.0f;
#pragma unroll
        for (int w = 0; w < BLOCK / 32; w++) s += red[w][tid];
        s *= g_invcnt[n];
        float r = 0.0f;
#pragma unroll
        for (int i = 0; i < IN; i++) r += h_in[(size_t)n * IN + i] * root[i * OUT + tid];
        float v = s + r + bias[tid];
        h_out[(size_t)n * OUT + tid] = fmaxf(v, 0.0f);
    }
}

// ---------------- CBT: pairwise L1 distance over 5 features ----------------
__global__ void cbt_kernel(const float* __restrict__ h3, float* __restrict__ out) {
    __shared__ float sh[NN * 5];
    int tid = threadIdx.x;
    for (int i = tid; i < NN * 5; i += blockDim.x) sh[i] = h3[i];
    __syncthreads();
    int a = blockIdx.x;
    float ha[5];
#pragma unroll
    for (int f = 0; f < 5; f++) ha[f] = sh[a * 5 + f];
    int bnode = tid;
    float s = 0.0f;
#pragma unroll
    for (int f = 0; f < 5; f++) s += fabsf(sh[bnode * 5 + f] - ha[f]);
    out[(size_t)a * NN + bnode] = s;
}

// ---------------- launch ----------------
extern "C" void kernel_launch(void* const* d_in, const int* in_sizes, int n_in,
                              void* d_out, int out_size) {
    const float* x    = (const float*)d_in[0];
    const float* ea   = (const float*)d_in[1];
    const int*   eidx = (const int*)d_in[2];   // int32 or int64 — detected on device
    const float *W1 = (const float*)d_in[3],  *b1 = (const float*)d_in[4];
    const float *root1 = (const float*)d_in[5], *bias1 = (const float*)d_in[6];
    const float *W2 = (const float*)d_in[7],  *b2 = (const float*)d_in[8];
    const float *root2 = (const float*)d_in[9], *bias2 = (const float*)d_in[10];
    const float *W3 = (const float*)d_in[11], *b3 = (const float*)d_in[12];
    const float *root3 = (const float*)d_in[13], *bias3 = (const float*)d_in[14];
    float* out = (float*)d_out;

    detect_kernel<<<1, NN>>>(eidx);
    hist_kernel<<<EE / 1024, 256>>>(eidx);
    scan_kernel<<<1, NN>>>();
    scatter_kernel<<<EE / 256, 256>>>(eidx, ea);

    float* h1; cudaGetSymbolAddress((void**)&h1, g_h1);
    float* h2; cudaGetSymbolAddress((void**)&h2, g_h2);
    float* h3; cudaGetSymbolAddress((void**)&h3, g_h3);

    nnconv_kernel<1, 36, 36, 256><<<NN, 256>>>(x,  W1, b1, root1, bias1, h1);
    nnconv_kernel<36, 24, 24, 256><<<NN, 256>>>(h1, W2, b2, root2, bias2, h2);
    nnconv_kernel<24, 5, 6, 256><<<NN, 256>>>(h2, W3, b3, root3, bias3, h3);
    cbt_kernel<<<NN, NN>>>(h3, out);
}

// round 5
// speedup vs baseline: 1.2676x; 1.2676x over previous
#include <cuda_runtime.h>
#include <cuda_bf16.h>

#define NN 512
#define EE (NN * NN)

// ---------------- scratch ----------------
__device__ int   g_is64;
__device__ int   g_nonzero;
__device__ int   g_cnt[NN];
__device__ int   g_off[NN];
__device__ int   g_start[NN + 1];
__device__ float g_invcnt[NN];
__device__ unsigned int g_eid_packed[EE];     // e (18b) | src<<18 (9b)
__device__ int   g_src_sorted[EE];
__device__ __align__(16) float g_ea_sorted[EE * 8];
__device__ __align__(16) float g_h1[NN * 36];
__device__ __align__(16) float g_h2[NN * 24];
__device__ __align__(16) float g_h3[NN * 5];

// ---------------- packed f32x2 helpers ----------------
__device__ __forceinline__ unsigned long long pk2(float lo, float hi) {
    unsigned long long r;
    asm("mov.b64 %0,{%1,%2};" : "=l"(r) : "f"(lo), "f"(hi));
    return r;
}
__device__ __forceinline__ void upk2(unsigned long long v, float& lo, float& hi) {
    asm("mov.b64 {%0,%1},%2;" : "=f"(lo), "=f"(hi) : "l"(v));
}
__device__ __forceinline__ unsigned long long ffma2(unsigned long long a,
                                                    unsigned long long b,
                                                    unsigned long long c) {
    unsigned long long d;
    asm("fma.rn.f32x2 %0,%1,%2,%3;" : "=l"(d) : "l"(a), "l"(b), "l"(c));
    return d;
}

__device__ __forceinline__ int load_src(const int* raw, int e, int is64) {
    return (is64 ? raw[2 * e] : raw[e]) & (NN - 1);
}
__device__ __forceinline__ int load_dst(const int* raw, int e, int is64) {
    return (is64 ? raw[2 * EE + 2 * e] : raw[EE + e]) & (NN - 1);
}

// ---------------- dtype detect + zero ----------------
__global__ void detect_kernel(const int* __restrict__ raw) {
    int t = threadIdx.x;
    if (t == 0) g_nonzero = 0;
    if (t < NN) g_cnt[t] = 0;
    __syncthreads();
    int idx = 2 * (t * (EE / 512)) + 1;
    if (t < 256 && raw[idx] != 0) atomicOr(&g_nonzero, 1);
    __syncthreads();
    if (t == 0) g_is64 = (g_nonzero == 0) ? 1 : 0;
}

// ---------------- histogram of dst ----------------
__global__ void hist_kernel(const int* __restrict__ raw) {
    __shared__ int h[NN];
    int tid = threadIdx.x;
    int is64 = g_is64;
    for (int i = tid; i < NN; i += blockDim.x) h[i] = 0;
    __syncthreads();
    int base = blockIdx.x * 1024;
#pragma unroll
    for (int k = 0; k < 4; k++) {
        int e = base + k * 256 + tid;
        atomicAdd(&h[load_dst(raw, e, is64)], 1);
    }
    __syncthreads();
    for (int i = tid; i < NN; i += blockDim.x)
        if (h[i]) atomicAdd(&g_cnt[i], h[i]);
}

// ---------------- exclusive scan ----------------
__global__ void scan_kernel() {
    __shared__ int sc[NN];
    int t = threadIdx.x;
    int c = g_cnt[t];
    sc[t] = c;
    __syncthreads();
    for (int off = 1; off < NN; off <<= 1) {
        int v = (t >= off) ? sc[t - off] : 0;
        __syncthreads();
        sc[t] += v;
        __syncthreads();
    }
    int excl = sc[t] - c;
    g_start[t] = excl;
    g_off[t]   = excl;
    if (t == NN - 1) g_start[NN] = sc[t];
    g_invcnt[t] = 1.0f / (float)(c > 1 ? c : 1);
}

// ---------------- phase A: write packed ids to sorted positions ----------------
__global__ void scatter_pos_kernel(const int* __restrict__ raw) {
    int e = blockIdx.x * 256 + threadIdx.x;
    int is64 = g_is64;
    int d = load_dst(raw, e, is64);
    int s = load_src(raw, e, is64);
    int pos = atomicAdd(&g_off[d], 1);
    g_eid_packed[pos] = (unsigned)e | ((unsigned)s << 18);
}

// ---------------- phase B: gather ea into sorted order (coalesced writes) ------
__global__ void permute_kernel(const float* __restrict__ ea) {
    int p = blockIdx.x * 256 + threadIdx.x;
    unsigned v = g_eid_packed[p];
    int e = (int)(v & 0x3FFFFu);
    int s = (int)(v >> 18);
    g_src_sorted[p] = s;
    const float* q = ea + (size_t)e * 6;
    float v0 = __ldg(q + 0), v1 = __ldg(q + 1), v2 = __ldg(q + 2);
    float v3 = __ldg(q + 3), v4 = __ldg(q + 4), v5 = __ldg(q + 5);
    float4* w = (float4*)(g_ea_sorted + (size_t)p * 8);
    w[0] = make_float4(v0, v1, v2, v3);
    w[1] = make_float4(v4, v5, 0.0f, 0.0f);
}

// ---------------- per-tile compute helpers ----------------
template <int NP>
__device__ __forceinline__ void edge_tile(const ulonglong2* tp,
                                          const unsigned long long* ea2,
                                          float xi, float* acc) {
#pragma unroll
    for (int p = 0; p < NP; p++) {
        ulonglong2 w01 = tp[4 * p + 0];
        ulonglong2 w23 = tp[4 * p + 1];
        ulonglong2 w45 = tp[4 * p + 2];
        ulonglong2 bb  = tp[4 * p + 3];
        unsigned long long t = bb.x;
        t = ffma2(ea2[0], w01.x, t);
        t = ffma2(ea2[1], w01.y, t);
        t = ffma2(ea2[2], w23.x, t);
        t = ffma2(ea2[3], w23.y, t);
        t = ffma2(ea2[4], w45.x, t);
        t = ffma2(ea2[5], w45.y, t);
        float t0, t1; upk2(t, t0, t1);
        acc[2 * p]     = fmaf(xi, fmaxf(t0, 0.0f), acc[2 * p]);
        acc[2 * p + 1] = fmaf(xi, fmaxf(t1, 0.0f), acc[2 * p + 1]);
    }
}

template <int NP>
__device__ __forceinline__ void edge_tile2(const ulonglong2* tp,
                                           const unsigned long long* eaA,
                                           const unsigned long long* eaB,
                                           float xiA, float xiB, float* acc) {
#pragma unroll
    for (int p = 0; p < NP; p++) {
        ulonglong2 w01 = tp[4 * p + 0];
        ulonglong2 w23 = tp[4 * p + 1];
        ulonglong2 w45 = tp[4 * p + 2];
        ulonglong2 bb  = tp[4 * p + 3];
        unsigned long long tA = bb.x, tB = bb.x;
        tA = ffma2(eaA[0], w01.x, tA);  tB = ffma2(eaB[0], w01.x, tB);
        tA = ffma2(eaA[1], w01.y, tA);  tB = ffma2(eaB[1], w01.y, tB);
        tA = ffma2(eaA[2], w23.x, tA);  tB = ffma2(eaB[2], w23.x, tB);
        tA = ffma2(eaA[3], w23.y, tA);  tB = ffma2(eaB[3], w23.y, tB);
        tA = ffma2(eaA[4], w45.x, tA);  tB = ffma2(eaB[4], w45.x, tB);
        tA = ffma2(eaA[5], w45.y, tA);  tB = ffma2(eaB[5], w45.y, tB);
        float a0, a1, b0, b1;
        upk2(tA, a0, a1); upk2(tB, b0, b1);
        float s0 = fmaf(xiA, fmaxf(a0, 0.0f), acc[2 * p]);
        float s1 = fmaf(xiA, fmaxf(a1, 0.0f), acc[2 * p + 1]);
        acc[2 * p]     = fmaf(xiB, fmaxf(b0, 0.0f), s0);
        acc[2 * p + 1] = fmaf(xiB, fmaxf(b1, 0.0f), s1);
    }
}

__device__ __forceinline__ void load_ea(int e, unsigned long long* ea2) {
    float4 eaA = *(const float4*)(g_ea_sorted + (size_t)e * 8);
    float4 eaB = *(const float4*)(g_ea_sorted + (size_t)e * 8 + 4);
    ea2[0] = pk2(eaA.x, eaA.x); ea2[1] = pk2(eaA.y, eaA.y);
    ea2[2] = pk2(eaA.z, eaA.z); ea2[3] = pk2(eaA.w, eaA.w);
    ea2[4] = pk2(eaB.x, eaB.x); ea2[5] = pk2(eaB.y, eaB.y);
}

// ---------------- fused NNConv layer (gather form) ----------------
template <int IN, int OUT, int OPAD, int BLOCK>
__global__ void __launch_bounds__(BLOCK) nnconv_kernel(
    const float* __restrict__ h_in,
    const float* __restrict__ W, const float* __restrict__ b,
    const float* __restrict__ root, const float* __restrict__ bias,
    float* __restrict__ h_out) {
    constexpr int NP = OPAD / 2;
    __shared__ __align__(16) float sW[IN * NP * 16];
    __shared__ float red[BLOCK / 32][OPAD];
    const int tid = threadIdx.x;

    for (int idx = tid; idx < IN * NP; idx += BLOCK) {
        int i = idx / NP, p = idx % NP;
        float* t = sW + idx * 16;
        int o0 = 2 * p, o1 = 2 * p + 1;
#pragma unroll
        for (int v = 0; v < 6; v++) {
            t[2 * v]     = (o0 < OUT) ? W[v * (IN * OUT) + i * OUT + o0] : 0.0f;
            t[2 * v + 1] = (o1 < OUT) ? W[v * (IN * OUT) + i * OUT + o1] : 0.0f;
        }
        t[12] = (o0 < OUT) ? b[i * OUT + o0] : 0.0f;
        t[13] = (o1 < OUT) ? b[i * OUT + o1] : 0.0f;
        t[14] = 0.0f; t[15] = 0.0f;
    }
    __syncthreads();

    const int n = blockIdx.x;
    const int e0 = g_start[n], e1 = g_start[n + 1];

    float acc[OPAD];
#pragma unroll
    for (int o = 0; o < OPAD; o++) acc[o] = 0.0f;

    int e = e0 + tid;
    // 2-edge unrolled main loop: W tile loaded once per pair of edges
    for (; e + BLOCK < e1; e += 2 * BLOCK) {
        int eA = e, eB = e + BLOCK;
        int sA = g_src_sorted[eA], sB = g_src_sorted[eB];
        unsigned long long eaA[6], eaB[6];
        load_ea(eA, eaA);
        load_ea(eB, eaB);
        if constexpr (IN == 1) {
            float xA = h_in[sA], xB = h_in[sB];
            edge_tile2<NP>((const ulonglong2*)sW, eaA, eaB, xA, xB, acc);
        } else {
#pragma unroll 1
            for (int i4 = 0; i4 < IN / 4; i4++) {
                float4 xvA = *(const float4*)(h_in + (size_t)sA * IN + 4 * i4);
                float4 xvB = *(const float4*)(h_in + (size_t)sB * IN + 4 * i4);
                float xsA[4] = {xvA.x, xvA.y, xvA.z, xvA.w};
                float xsB[4] = {xvB.x, xvB.y, xvB.z, xvB.w};
#pragma unroll
                for (int su = 0; su < 4; su++) {
                    const ulonglong2* tp =
                        (const ulonglong2*)(sW + (size_t)(i4 * 4 + su) * NP * 16);
                    edge_tile2<NP>(tp, eaA, eaB, xsA[su], xsB[su], acc);
                }
            }
        }
    }
    // tail: at most one more edge for this thread
    if (e < e1) {
        int s = g_src_sorted[e];
        unsigned long long ea2[6];
        load_ea(e, ea2);
        if constexpr (IN == 1) {
            float xi = h_in[s];
            edge_tile<NP>((const ulonglong2*)sW, ea2, xi, acc);
        } else {
#pragma unroll 1
            for (int i4 = 0; i4 < IN / 4; i4++) {
                float4 xv = *(const float4*)(h_in + (size_t)s * IN + 4 * i4);
                float xs[4] = {xv.x, xv.y, xv.z, xv.w};
#pragma unroll
                for (int su = 0; su < 4; su++) {
                    const ulonglong2* tp =
                        (const ulonglong2*)(sW + (size_t)(i4 * 4 + su) * NP * 16);
                    edge_tile<NP>(tp, ea2, xs[su], acc);
                }
            }
        }
    }

    // warp reduce
#pragma unroll
    for (int o = 0; o < OPAD; o++) {
        float v = acc[o];
        v += __shfl_down_sync(0xffffffffu, v, 16);
        v += __shfl_down_sync(0xffffffffu, v, 8);
        v += __shfl_down_sync(0xffffffffu, v, 4);
        v += __shfl_down_sync(0xffffffffu, v, 2);
        v += __shfl_down_sync(0xffffffffu, v, 1);
        acc[o] = v;
    }
    if ((tid & 31) == 0) {
#pragma unroll
        for (int o = 0; o < OPAD; o++) red[tid >> 5][o] = acc[o];
    }
    __syncthreads();

    if (tid < OUT) {
        float s = 0.0f;
#pragma unroll
        for (int w = 0; w < BLOCK / 32; w++) s += red[w][tid];
        s *= g_invcnt[n];
        float r = 0.0f;
#pragma unroll
        for (int i = 0; i < IN; i++) r += h_in[(size_t)n * IN + i] * root[i * OUT + tid];
        float v = s + r + bias[tid];
        h_out[(size_t)n * OUT + tid] = fmaxf(v, 0.0f);
    }
}

// ---------------- CBT ----------------
__global__ void cbt_kernel(const float* __restrict__ h3, float* __restrict__ out) {
    __shared__ float sh[NN * 5];
    int tid = threadIdx.x;
    for (int i = tid; i < NN * 5; i += blockDim.x) sh[i] = h3[i];
    __syncthreads();
    int a = blockIdx.x;
    float ha[5];
#pragma unroll
    for (int f = 0; f < 5; f++) ha[f] = sh[a * 5 + f];
    float s = 0.0f;
#pragma unroll
    for (int f = 0; f < 5; f++) s += fabsf(sh[tid * 5 + f] - ha[f]);
    out[(size_t)a * NN + tid] = s;
}

// ---------------- launch ----------------
extern "C" void kernel_launch(void* const* d_in, const int* in_sizes, int n_in,
                              void* d_out, int out_size) {
    const float* x    = (const float*)d_in[0];
    const float* ea   = (const float*)d_in[1];
    const int*   eidx = (const int*)d_in[2];
    const float *W1 = (const float*)d_in[3],  *b1 = (const float*)d_in[4];
    const float *root1 = (const float*)d_in[5], *bias1 = (const float*)d_in[6];
    const float *W2 = (const float*)d_in[7],  *b2 = (const float*)d_in[8];
    const float *root2 = (const float*)d_in[9], *bias2 = (const float*)d_in[10];
    const float *W3 = (const float*)d_in[11], *b3 = (const float*)d_in[12];
    const float *root3 = (const float*)d_in[13], *bias3 = (const float*)d_in[14];
    float* out = (float*)d_out;

    detect_kernel<<<1, NN>>>(eidx);
    hist_kernel<<<EE / 1024, 256>>>(eidx);
    scan_kernel<<<1, NN>>>();
    scatter_pos_kernel<<<EE / 256, 256>>>(eidx);
    permute_kernel<<<EE / 256, 256>>>(ea);

    float* h1; cudaGetSymbolAddress((void**)&h1, g_h1);
    float* h2; cudaGetSymbolAddress((void**)&h2, g_h2);
    float* h3; cudaGetSymbolAddress((void**)&h3, g_h3);

    nnconv_kernel<1, 36, 36, 128><<<NN, 128>>>(x,  W1, b1, root1, bias1, h1);
    nnconv_kernel<36, 24, 24, 128><<<NN, 128>>>(h1, W2, b2, root2, bias2, h2);
    nnconv_kernel<24, 5, 6, 128><<<NN, 128>>>(h2, W3, b3, root3, bias3, h3);
    cbt_kernel<<<NN, NN>>>(h3, out);
}